// round 2
// baseline (speedup 1.0000x reference)
#include <cuda_runtime.h>
#include <stdint.h>

// Problem constants (fixed shapes for this problem)
#define N_GENES 20000
#define N_DRUGS 4000
#define IN_C    1024
#define OUT_C   512
#define N_EDGES 262144

// ---------------- device scratch (static, no allocation) ----------------
__device__ int   g_row_deg[N_GENES];
__device__ int   g_col_deg[N_DRUGS];
__device__ int   g_offs[N_DRUGS];      // exclusive prefix of col_deg
__device__ int   g_cursor[N_DRUGS];
__device__ int   g_active[N_GENES];    // compact list of genes with deg>0
__device__ int   g_rowmap[N_GENES];    // gene id -> compact row index
__device__ int   g_nactive;
__device__ int   g_is64;               // 1 if edge_index is int64, 0 if int32
__device__ float g_xw[(size_t)N_GENES * OUT_C];  // compacted XW rows
__device__ int   g_sidx[N_EDGES];      // sorted-by-dst: compact row index of src
__device__ float g_scoef[N_EDGES];     // sorted-by-dst: edge coefficient

// ---------------- edge dtype detection ----------------
// If the buffer is int64 (little-endian) with values < N_GENES, every odd
// 32-bit word (the high half) is zero. If it is int32 random ids in
// [0, N_DRUGS), odd words are data and are overwhelmingly nonzero.
__global__ void k_detect(const int* __restrict__ ei32) {
    __shared__ int any_nonzero;
    if (threadIdx.x == 0) any_nonzero = 0;
    __syncthreads();
    // inspect odd words of the first 8192 ints (covers 4096 edges either way)
    for (int i = threadIdx.x * 2 + 1; i < 8192; i += blockDim.x * 2) {
        if (ei32[i] != 0) any_nonzero = 1;
    }
    __syncthreads();
    if (threadIdx.x == 0) g_is64 = any_nonzero ? 0 : 1;
}

__device__ __forceinline__ void load_edge(const void* ei, int e, int& s, int& d) {
    if (g_is64) {
        const long long* p = (const long long*)ei;
        s = (int)p[e];
        d = (int)p[N_EDGES + e];
    } else {
        const int* p = (const int*)ei;
        s = p[e];
        d = p[N_EDGES + e];
    }
}

// ---------------- kernels ----------------

__global__ void k_zero() {
    int i = blockIdx.x * blockDim.x + threadIdx.x;
    if (i < N_GENES) g_row_deg[i] = 0;
    if (i < N_DRUGS) { g_col_deg[i] = 0; g_cursor[i] = 0; }
    if (i == 0) g_nactive = 0;
}

__global__ void k_degree(const void* __restrict__ ei) {
    int e = blockIdx.x * blockDim.x + threadIdx.x;
    if (e >= N_EDGES) return;
    int s, d;
    load_edge(ei, e, s, d);
    if (s >= 0 && s < N_GENES) atomicAdd(&g_row_deg[s], 1);
    if (d >= 0 && d < N_DRUGS) atomicAdd(&g_col_deg[d], 1);
}

__global__ void k_compact() {
    int g = blockIdx.x * blockDim.x + threadIdx.x;
    if (g >= N_GENES) return;
    if (g_row_deg[g] > 0) {
        int idx = atomicAdd(&g_nactive, 1);
        g_active[idx] = g;
        g_rowmap[g] = idx;
    }
}

// exclusive scan of g_col_deg (4000 ints) -> g_offs. One block of 1024 threads.
__global__ void k_scan() {
    __shared__ int sh[1024];
    int t = threadIdx.x;
    int base = t * 4;
    int v[4];
    int sum = 0;
#pragma unroll
    for (int i = 0; i < 4; i++) {
        v[i] = (base + i < N_DRUGS) ? g_col_deg[base + i] : 0;
        sum += v[i];
    }
    sh[t] = sum;
    __syncthreads();
    // Hillis-Steele inclusive scan over 1024 partials
    for (int d = 1; d < 1024; d <<= 1) {
        int x = (t >= d) ? sh[t - d] : 0;
        __syncthreads();
        sh[t] += x;
        __syncthreads();
    }
    int excl = (t > 0) ? sh[t - 1] : 0;
    int run = excl;
#pragma unroll
    for (int i = 0; i < 4; i++) {
        if (base + i < N_DRUGS) {
            g_offs[base + i] = run;
            run += v[i];
        }
    }
}

// per edge: compute coef, place (rowmap[src], coef) into dst-sorted arrays
__global__ void k_coef_scatter(const void* __restrict__ ei) {
    int e = blockIdx.x * blockDim.x + threadIdx.x;
    if (e >= N_EDGES) return;
    int s, d;
    load_edge(ei, e, s, d);
    if (s < 0 || s >= N_GENES || d < 0 || d >= N_DRUGS) return;
    float c = rsqrtf((float)g_row_deg[s]) * rsqrtf((float)g_col_deg[d]);
    int p = g_offs[d] + atomicAdd(&g_cursor[d], 1);
    g_sidx[p] = g_rowmap[s];
    g_scoef[p] = c;
}

// SGEMM on compacted rows: g_xw[r, :] = X[g_active[r], :] @ W
// Tiles: BM=64, BN=64, BK=16, 256 threads, 4x4 per thread, double-buffered smem.
#define BM 64
#define BN 64
#define BK 16

__global__ __launch_bounds__(256) void k_gemm(const float* __restrict__ X,
                                              const float* __restrict__ W) {
    int nact = g_nactive;
    int bm = blockIdx.y, bn = blockIdx.x;
    if (bm * BM >= nact) return;

    __shared__ __align__(16) float As[2][BK][BM];  // transposed A tile
    __shared__ __align__(16) float Bs[2][BK][BN];

    int tid = threadIdx.x;
    // A tile load: BM x BK floats, each thread one float4 along K
    int ar = tid >> 2;           // 0..63
    int ac = (tid & 3) * 4;      // 0,4,8,12
    // B tile load: BK x BN floats, each thread one float4 along N
    int br = tid >> 4;           // 0..15
    int bc = (tid & 15) * 4;     // 0..60

    int grow = bm * BM + ar;
    bool av = grow < nact;
    const float* aptr = X;       // dummy if invalid
    if (av) aptr = X + (size_t)g_active[grow] * IN_C + ac;
    const float* bptr = W + (size_t)br * OUT_C + bn * BN + bc;

    int tx = tid & 15, ty = tid >> 4;  // 16x16 thread grid, 4x4 each
    float acc[4][4] = {};

    float4 af = av ? *(const float4*)aptr : make_float4(0.f, 0.f, 0.f, 0.f);
    float4 bf = *(const float4*)bptr;
    As[0][ac + 0][ar] = af.x;
    As[0][ac + 1][ar] = af.y;
    As[0][ac + 2][ar] = af.z;
    As[0][ac + 3][ar] = af.w;
    *(float4*)&Bs[0][br][bc] = bf;
    __syncthreads();

    const int NK = IN_C / BK;  // 64
    for (int kt = 0; kt < NK; ++kt) {
        int cur = kt & 1, nxt = cur ^ 1;
        if (kt + 1 < NK) {
            af = av ? *(const float4*)(aptr + (size_t)(kt + 1) * BK)
                    : make_float4(0.f, 0.f, 0.f, 0.f);
            bf = *(const float4*)(bptr + (size_t)(kt + 1) * BK * OUT_C);
        }
#pragma unroll
        for (int k = 0; k < BK; k++) {
            float4 a4 = *(const float4*)&As[cur][k][ty * 4];
            float4 b4 = *(const float4*)&Bs[cur][k][tx * 4];
            acc[0][0] = fmaf(a4.x, b4.x, acc[0][0]);
            acc[0][1] = fmaf(a4.x, b4.y, acc[0][1]);
            acc[0][2] = fmaf(a4.x, b4.z, acc[0][2]);
            acc[0][3] = fmaf(a4.x, b4.w, acc[0][3]);
            acc[1][0] = fmaf(a4.y, b4.x, acc[1][0]);
            acc[1][1] = fmaf(a4.y, b4.y, acc[1][1]);
            acc[1][2] = fmaf(a4.y, b4.z, acc[1][2]);
            acc[1][3] = fmaf(a4.y, b4.w, acc[1][3]);
            acc[2][0] = fmaf(a4.z, b4.x, acc[2][0]);
            acc[2][1] = fmaf(a4.z, b4.y, acc[2][1]);
            acc[2][2] = fmaf(a4.z, b4.z, acc[2][2]);
            acc[2][3] = fmaf(a4.z, b4.w, acc[2][3]);
            acc[3][0] = fmaf(a4.w, b4.x, acc[3][0]);
            acc[3][1] = fmaf(a4.w, b4.y, acc[3][1]);
            acc[3][2] = fmaf(a4.w, b4.z, acc[3][2]);
            acc[3][3] = fmaf(a4.w, b4.w, acc[3][3]);
        }
        if (kt + 1 < NK) {
            As[nxt][ac + 0][ar] = af.x;
            As[nxt][ac + 1][ar] = af.y;
            As[nxt][ac + 2][ar] = af.z;
            As[nxt][ac + 3][ar] = af.w;
            *(float4*)&Bs[nxt][br][bc] = bf;
        }
        __syncthreads();
    }

#pragma unroll
    for (int i = 0; i < 4; i++) {
        int r = bm * BM + ty * 4 + i;
        if (r < nact) {
            float4 o = make_float4(acc[i][0], acc[i][1], acc[i][2], acc[i][3]);
            *(float4*)&g_xw[(size_t)r * OUT_C + bn * BN + tx * 4] = o;
        }
    }
}

// one block per dst: register-accumulate all its edges' scaled XW rows, add bias
__global__ __launch_bounds__(128) void k_aggregate(const float* __restrict__ bias,
                                                   float* __restrict__ out) {
    int d = blockIdx.x;
    int t = threadIdx.x;  // 128 threads, each owns a float4 of the 512 channels
    int beg = g_offs[d];
    int n = g_col_deg[d];
    const float4* xw4 = (const float4*)g_xw;

    float4 a0 = make_float4(0.f, 0.f, 0.f, 0.f);
    float4 a1 = make_float4(0.f, 0.f, 0.f, 0.f);
    int i = beg, end = beg + n;
    for (; i + 1 < end; i += 2) {
        int s0 = g_sidx[i], s1 = g_sidx[i + 1];
        float c0 = g_scoef[i], c1 = g_scoef[i + 1];
        float4 v0 = xw4[(size_t)s0 * (OUT_C / 4) + t];
        float4 v1 = xw4[(size_t)s1 * (OUT_C / 4) + t];
        a0.x = fmaf(v0.x, c0, a0.x);
        a0.y = fmaf(v0.y, c0, a0.y);
        a0.z = fmaf(v0.z, c0, a0.z);
        a0.w = fmaf(v0.w, c0, a0.w);
        a1.x = fmaf(v1.x, c1, a1.x);
        a1.y = fmaf(v1.y, c1, a1.y);
        a1.z = fmaf(v1.z, c1, a1.z);
        a1.w = fmaf(v1.w, c1, a1.w);
    }
    if (i < end) {
        int s0 = g_sidx[i];
        float c0 = g_scoef[i];
        float4 v0 = xw4[(size_t)s0 * (OUT_C / 4) + t];
        a0.x = fmaf(v0.x, c0, a0.x);
        a0.y = fmaf(v0.y, c0, a0.y);
        a0.z = fmaf(v0.z, c0, a0.z);
        a0.w = fmaf(v0.w, c0, a0.w);
    }
    float4 b = ((const float4*)bias)[t];
    float4 o = make_float4(a0.x + a1.x + b.x, a0.y + a1.y + b.y,
                           a0.z + a1.z + b.z, a0.w + a1.w + b.w);
    ((float4*)out)[(size_t)d * (OUT_C / 4) + t] = o;
}

// ---------------- launch ----------------
extern "C" void kernel_launch(void* const* d_in, const int* in_sizes, int n_in,
                              void* d_out, int out_size) {
    const float* x = (const float*)d_in[0];
    const float* w = (const float*)d_in[1];
    const float* bias = (const float*)d_in[2];
    const void* ei = d_in[3];
    float* out = (float*)d_out;

    k_detect<<<1, 256>>>((const int*)ei);
    k_zero<<<(N_GENES + 255) / 256, 256>>>();
    k_degree<<<(N_EDGES + 255) / 256, 256>>>(ei);
    k_compact<<<(N_GENES + 255) / 256, 256>>>();
    k_scan<<<1, 1024>>>();
    k_coef_scatter<<<(N_EDGES + 255) / 256, 256>>>(ei);

    dim3 gemm_grid(OUT_C / BN, (N_GENES + BM - 1) / BM);
    k_gemm<<<gemm_grid, 256>>>(x, w);

    k_aggregate<<<N_DRUGS, 128>>>(bias, out);
}

// round 4
// speedup vs baseline: 1.4365x; 1.4365x over previous
#include <cuda_runtime.h>
#include <stdint.h>

// Problem constants (fixed shapes for this problem)
#define N_GENES 20000
#define N_DRUGS 4000
#define IN_C    1024
#define OUT_C   512
#define N_EDGES 262144

// ---------------- device scratch (static, no allocation) ----------------
__device__ int   g_row_deg[N_GENES];
__device__ int   g_col_deg[N_DRUGS];
__device__ int   g_offs[N_DRUGS];
__device__ int   g_cursor[N_DRUGS];
__device__ int   g_active[N_GENES];
__device__ int   g_rowmap[N_GENES];
__device__ int   g_nactive;
__device__ int   g_is64;
__device__ float g_xw[(size_t)N_GENES * OUT_C];
__device__ int   g_sidx[N_EDGES];
__device__ float g_scoef[N_EDGES];

// ---------------- helpers ----------------
__device__ __forceinline__ void split_tf32(float x, uint32_t& h, uint32_t& l) {
    asm("cvt.rna.tf32.f32 %0, %1;" : "=r"(h) : "f"(x));
    float r = x - __uint_as_float(h);
    asm("cvt.rna.tf32.f32 %0, %1;" : "=r"(l) : "f"(r));
}

__device__ __forceinline__ void mma_tf32(float* c, const uint32_t* a, const uint32_t* b) {
    asm volatile(
        "mma.sync.aligned.m16n8k8.row.col.f32.tf32.tf32.f32 "
        "{%0,%1,%2,%3}, {%4,%5,%6,%7}, {%8,%9}, {%0,%1,%2,%3};"
        : "+f"(c[0]), "+f"(c[1]), "+f"(c[2]), "+f"(c[3])
        : "r"(a[0]), "r"(a[1]), "r"(a[2]), "r"(a[3]), "r"(b[0]), "r"(b[1]));
}

// ---------------- edge dtype detection ----------------
__global__ void k_detect(const int* __restrict__ ei32) {
    __shared__ int any_nonzero;
    if (threadIdx.x == 0) any_nonzero = 0;
    __syncthreads();
    for (int i = threadIdx.x * 2 + 1; i < 8192; i += blockDim.x * 2) {
        if (ei32[i] != 0) any_nonzero = 1;
    }
    __syncthreads();
    if (threadIdx.x == 0) g_is64 = any_nonzero ? 0 : 1;
}

__device__ __forceinline__ void load_edge(const void* ei, int e, int& s, int& d) {
    if (g_is64) {
        const long long* p = (const long long*)ei;
        s = (int)p[e];
        d = (int)p[N_EDGES + e];
    } else {
        const int* p = (const int*)ei;
        s = p[e];
        d = p[N_EDGES + e];
    }
}

// ---------------- preprocessing ----------------
__global__ void k_zero() {
    int i = blockIdx.x * blockDim.x + threadIdx.x;
    if (i < N_GENES) g_row_deg[i] = 0;
    if (i < N_DRUGS) { g_col_deg[i] = 0; g_cursor[i] = 0; }
    if (i == 0) g_nactive = 0;
}

__global__ void k_degree(const void* __restrict__ ei) {
    int e = blockIdx.x * blockDim.x + threadIdx.x;
    if (e >= N_EDGES) return;
    int s, d;
    load_edge(ei, e, s, d);
    if (s >= 0 && s < N_GENES) atomicAdd(&g_row_deg[s], 1);
    if (d >= 0 && d < N_DRUGS) atomicAdd(&g_col_deg[d], 1);
}

__global__ void k_compact() {
    int g = blockIdx.x * blockDim.x + threadIdx.x;
    if (g >= N_GENES) return;
    if (g_row_deg[g] > 0) {
        int idx = atomicAdd(&g_nactive, 1);
        g_active[idx] = g;
        g_rowmap[g] = idx;
    }
}

__global__ void k_scan() {
    __shared__ int sh[1024];
    int t = threadIdx.x;
    int base = t * 4;
    int v[4];
    int sum = 0;
#pragma unroll
    for (int i = 0; i < 4; i++) {
        v[i] = (base + i < N_DRUGS) ? g_col_deg[base + i] : 0;
        sum += v[i];
    }
    sh[t] = sum;
    __syncthreads();
    for (int d = 1; d < 1024; d <<= 1) {
        int x = (t >= d) ? sh[t - d] : 0;
        __syncthreads();
        sh[t] += x;
        __syncthreads();
    }
    int excl = (t > 0) ? sh[t - 1] : 0;
    int run = excl;
#pragma unroll
    for (int i = 0; i < 4; i++) {
        if (base + i < N_DRUGS) {
            g_offs[base + i] = run;
            run += v[i];
        }
    }
}

__global__ void k_coef_scatter(const void* __restrict__ ei) {
    int e = blockIdx.x * blockDim.x + threadIdx.x;
    if (e >= N_EDGES) return;
    int s, d;
    load_edge(ei, e, s, d);
    if (s < 0 || s >= N_GENES || d < 0 || d >= N_DRUGS) return;
    float c = rsqrtf((float)g_row_deg[s]) * rsqrtf((float)g_col_deg[d]);
    int p = g_offs[d] + atomicAdd(&g_cursor[d], 1);
    g_sidx[p] = g_rowmap[s];
    g_scoef[p] = c;
}

// ---------------- tensor-core tf32x3 GEMM via mma.sync ----------------
// g_xw[m, :] = X[g_active[m], :] @ W  with hi/lo tf32 split (3 terms).
// CTA tile 128x128, BK=32, 8 warps each 64x32 (4 m-frags x 4 n-frags).
#define GM 128
#define GN 128
#define KT 32
#define NKT (IN_C / KT)   // 32

// smem word layouts: A[128][36] (pad 4), B[32][136] (pad 8); hi+lo planes; 2 buffers
#define A_STRIDE 36
#define B_STRIDE 136
#define A_WORDS (128 * A_STRIDE)          // 4608
#define B_WORDS (32 * B_STRIDE)           // 4352
#define BUF_WORDS (2 * A_WORDS + 2 * B_WORDS)  // 17920 words = 71680 B
#define AHI_OFF 0
#define ALO_OFF A_WORDS
#define BHI_OFF (2 * A_WORDS)
#define BLO_OFF (2 * A_WORDS + B_WORDS)
#define GEMM_SMEM (2 * BUF_WORDS * 4)     // 143360 B

__global__ __launch_bounds__(256) void k_gemm_mma(const float* __restrict__ X,
                                                  const float* __restrict__ W) {
    const int nact = g_nactive;
    const int m0 = blockIdx.y * GM;
    if (m0 >= nact) return;
    const int n0 = blockIdx.x * GN;

    extern __shared__ __align__(16) uint32_t smem[];

    const int tid = threadIdx.x;
    const int wid = tid >> 5;
    const int lane = tid & 31;
    const int g = lane >> 2;        // 0..7
    const int tig = lane & 3;       // 0..3
    const int mwarp = (wid & 1) * 64;   // 2 warps along M
    const int nwarp = (wid >> 1) * 32;  // 4 warps along N

    // ---- per-thread staging assignments (fixed across k-tiles) ----
    // A: idx = p*256+tid -> m = idx>>3 (0..127), kq = idx&7 (float4 within 32 k)
    const float* aptr[4];
    int a_st[4];
    bool a_ok[4];
#pragma unroll
    for (int p = 0; p < 4; p++) {
        int idx = p * 256 + tid;
        int m = idx >> 3, kq = idx & 7;
        a_ok[p] = (m0 + m) < nact;
        aptr[p] = a_ok[p] ? (X + (size_t)g_active[m0 + m] * IN_C + kq * 4) : X;
        a_st[p] = m * A_STRIDE + kq * 4;
    }
    // B: idx = p*256+tid -> k = idx>>5 (0..31), nq = idx&31 (float4 within 128 n)
    const float* bptr[4];
    int b_st[4];
#pragma unroll
    for (int p = 0; p < 4; p++) {
        int idx = p * 256 + tid;
        int k = idx >> 5, nq = idx & 31;
        bptr[p] = W + (size_t)k * OUT_C + n0 + nq * 4;
        b_st[p] = k * B_STRIDE + nq * 4;
    }

    float acc[4][4][4];
#pragma unroll
    for (int i = 0; i < 4; i++)
#pragma unroll
        for (int j = 0; j < 4; j++)
#pragma unroll
            for (int r = 0; r < 4; r++) acc[i][j][r] = 0.f;

    float4 apre[4], bpre[4];
    // prefetch k-tile 0
#pragma unroll
    for (int p = 0; p < 4; p++) {
        apre[p] = a_ok[p] ? *(const float4*)(aptr[p]) : make_float4(0.f, 0.f, 0.f, 0.f);
        bpre[p] = *(const float4*)(bptr[p]);
    }
    // split + store buf 0
    {
        uint32_t* buf = smem;
#pragma unroll
        for (int p = 0; p < 4; p++) {
            uint4 h, l;
            split_tf32(apre[p].x, h.x, l.x);
            split_tf32(apre[p].y, h.y, l.y);
            split_tf32(apre[p].z, h.z, l.z);
            split_tf32(apre[p].w, h.w, l.w);
            *(uint4*)(buf + AHI_OFF + a_st[p]) = h;
            *(uint4*)(buf + ALO_OFF + a_st[p]) = l;
            split_tf32(bpre[p].x, h.x, l.x);
            split_tf32(bpre[p].y, h.y, l.y);
            split_tf32(bpre[p].z, h.z, l.z);
            split_tf32(bpre[p].w, h.w, l.w);
            *(uint4*)(buf + BHI_OFF + b_st[p]) = h;
            *(uint4*)(buf + BLO_OFF + b_st[p]) = l;
        }
    }
    __syncthreads();

#pragma unroll 1
    for (int kt = 0; kt < NKT; kt++) {
        // prefetch next k-tile from global
        if (kt + 1 < NKT) {
#pragma unroll
            for (int p = 0; p < 4; p++) {
                apre[p] = a_ok[p] ? *(const float4*)(aptr[p] + (kt + 1) * KT)
                                  : make_float4(0.f, 0.f, 0.f, 0.f);
                bpre[p] = *(const float4*)(bptr[p] + (size_t)(kt + 1) * KT * OUT_C);
            }
        }

        // compute on current buffer
        const uint32_t* buf = smem + (kt & 1) * BUF_WORDS;
        const uint32_t* Ah = buf + AHI_OFF;
        const uint32_t* Al = buf + ALO_OFF;
        const uint32_t* Bh = buf + BHI_OFF;
        const uint32_t* Bl = buf + BLO_OFF;

#pragma unroll
        for (int kk = 0; kk < 4; kk++) {
            const int kb = kk * 8;
            uint32_t ah[4][4], al[4][4], bh[4][2], bl[4][2];
#pragma unroll
            for (int mf = 0; mf < 4; mf++) {
                int r0 = (mwarp + mf * 16 + g) * A_STRIDE + kb + tig;
                int r1 = r0 + 8 * A_STRIDE;
                ah[mf][0] = Ah[r0];
                ah[mf][1] = Ah[r1];
                ah[mf][2] = Ah[r0 + 4];
                ah[mf][3] = Ah[r1 + 4];
                al[mf][0] = Al[r0];
                al[mf][1] = Al[r1];
                al[mf][2] = Al[r0 + 4];
                al[mf][3] = Al[r1 + 4];
            }
#pragma unroll
            for (int nf = 0; nf < 4; nf++) {
                int c0 = (kb + tig) * B_STRIDE + nwarp + nf * 8 + g;
                int c1 = c0 + 4 * B_STRIDE;
                bh[nf][0] = Bh[c0];
                bh[nf][1] = Bh[c1];
                bl[nf][0] = Bl[c0];
                bl[nf][1] = Bl[c1];
            }
#pragma unroll
            for (int mf = 0; mf < 4; mf++) {
#pragma unroll
                for (int nf = 0; nf < 4; nf++) {
                    mma_tf32(acc[mf][nf], ah[mf], bh[nf]);
                    mma_tf32(acc[mf][nf], ah[mf], bl[nf]);
                    mma_tf32(acc[mf][nf], al[mf], bh[nf]);
                }
            }
        }

        // split + store next buffer
        if (kt + 1 < NKT) {
            uint32_t* nbuf = smem + ((kt + 1) & 1) * BUF_WORDS;
#pragma unroll
            for (int p = 0; p < 4; p++) {
                uint4 h, l;
                split_tf32(apre[p].x, h.x, l.x);
                split_tf32(apre[p].y, h.y, l.y);
                split_tf32(apre[p].z, h.z, l.z);
                split_tf32(apre[p].w, h.w, l.w);
                *(uint4*)(nbuf + AHI_OFF + a_st[p]) = h;
                *(uint4*)(nbuf + ALO_OFF + a_st[p]) = l;
                split_tf32(bpre[p].x, h.x, l.x);
                split_tf32(bpre[p].y, h.y, l.y);
                split_tf32(bpre[p].z, h.z, l.z);
                split_tf32(bpre[p].w, h.w, l.w);
                *(uint4*)(nbuf + BHI_OFF + b_st[p]) = h;
                *(uint4*)(nbuf + BLO_OFF + b_st[p]) = l;
            }
        }
        __syncthreads();
    }

    // ---- epilogue: direct stores (32B sectors, L2-resident for aggregate) ----
#pragma unroll
    for (int mf = 0; mf < 4; mf++) {
        int row0 = m0 + mwarp + mf * 16 + g;
        int row1 = row0 + 8;
#pragma unroll
        for (int nf = 0; nf < 4; nf++) {
            int col = n0 + nwarp + nf * 8 + tig * 2;
            if (row0 < nact)
                *(float2*)(g_xw + (size_t)row0 * OUT_C + col) =
                    make_float2(acc[mf][nf][0], acc[mf][nf][1]);
            if (row1 < nact)
                *(float2*)(g_xw + (size_t)row1 * OUT_C + col) =
                    make_float2(acc[mf][nf][2], acc[mf][nf][3]);
        }
    }
}

// ---------------- aggregation ----------------
__global__ __launch_bounds__(128) void k_aggregate(const float* __restrict__ bias,
                                                   float* __restrict__ out) {
    int d = blockIdx.x;
    int t = threadIdx.x;
    int beg = g_offs[d];
    int n = g_col_deg[d];
    const float4* xw4 = (const float4*)g_xw;

    float4 a0 = make_float4(0.f, 0.f, 0.f, 0.f);
    float4 a1 = make_float4(0.f, 0.f, 0.f, 0.f);
    int i = beg, end = beg + n;
    for (; i + 1 < end; i += 2) {
        int s0 = g_sidx[i], s1 = g_sidx[i + 1];
        float c0 = g_scoef[i], c1 = g_scoef[i + 1];
        float4 v0 = xw4[(size_t)s0 * (OUT_C / 4) + t];
        float4 v1 = xw4[(size_t)s1 * (OUT_C / 4) + t];
        a0.x = fmaf(v0.x, c0, a0.x);
        a0.y = fmaf(v0.y, c0, a0.y);
        a0.z = fmaf(v0.z, c0, a0.z);
        a0.w = fmaf(v0.w, c0, a0.w);
        a1.x = fmaf(v1.x, c1, a1.x);
        a1.y = fmaf(v1.y, c1, a1.y);
        a1.z = fmaf(v1.z, c1, a1.z);
        a1.w = fmaf(v1.w, c1, a1.w);
    }
    if (i < end) {
        int s0 = g_sidx[i];
        float c0 = g_scoef[i];
        float4 v0 = xw4[(size_t)s0 * (OUT_C / 4) + t];
        a0.x = fmaf(v0.x, c0, a0.x);
        a0.y = fmaf(v0.y, c0, a0.y);
        a0.z = fmaf(v0.z, c0, a0.z);
        a0.w = fmaf(v0.w, c0, a0.w);
    }
    float4 b = ((const float4*)bias)[t];
    float4 o = make_float4(a0.x + a1.x + b.x, a0.y + a1.y + b.y,
                           a0.z + a1.z + b.z, a0.w + a1.w + b.w);
    ((float4*)out)[(size_t)d * (OUT_C / 4) + t] = o;
}

// ---------------- launch ----------------
extern "C" void kernel_launch(void* const* d_in, const int* in_sizes, int n_in,
                              void* d_out, int out_size) {
    const float* x = (const float*)d_in[0];
    const float* w = (const float*)d_in[1];
    const float* bias = (const float*)d_in[2];
    const void* ei = d_in[3];
    float* out = (float*)d_out;

    static bool attr_set = false;
    if (!attr_set) {
        cudaFuncSetAttribute(k_gemm_mma, cudaFuncAttributeMaxDynamicSharedMemorySize,
                             GEMM_SMEM);
        attr_set = true;
    }

    k_detect<<<1, 256>>>((const int*)ei);
    k_zero<<<(N_GENES + 255) / 256, 256>>>();
    k_degree<<<(N_EDGES + 255) / 256, 256>>>(ei);
    k_compact<<<(N_GENES + 255) / 256, 256>>>();
    k_scan<<<1, 1024>>>();
    k_coef_scatter<<<(N_EDGES + 255) / 256, 256>>>(ei);

    dim3 gemm_grid(OUT_C / GN, (N_GENES + GM - 1) / GM);
    k_gemm_mma<<<gemm_grid, 256, GEMM_SMEM>>>(x, w);

    k_aggregate<<<N_DRUGS, 128>>>(bias, out);
}

// round 5
// speedup vs baseline: 1.7018x; 1.1847x over previous
#include <cuda_runtime.h>
#include <stdint.h>

// Problem constants
#define N_GENES 20000
#define N_DRUGS 4000
#define IN_C    1024
#define OUT_C   512
#define N_EDGES 262144

// ---------------- device scratch ----------------
__device__ int   g_row_deg[N_GENES];
__device__ int   g_col_deg[N_DRUGS];
__device__ int   g_offs[N_DRUGS];
__device__ int   g_cursor[N_DRUGS];
__device__ int   g_active[N_GENES];
__device__ int   g_rowmap[N_GENES];
__device__ float g_rowscale[N_GENES];   // rsqrt(row_deg) per compact row
__device__ int   g_nactive;
__device__ int   g_is64;
__device__ float g_xw[(size_t)N_GENES * OUT_C];  // row-scaled XW rows
__device__ int   g_sidx[N_EDGES];

// ---------------- helpers ----------------
// pack two floats into bf16x2 (f0 -> low, f1 -> high) and the bf16 residuals
__device__ __forceinline__ void split2_bf16(float f0, float f1,
                                            uint32_t& h, uint32_t& l) {
    asm("cvt.rn.bf16x2.f32 %0, %1, %2;" : "=r"(h) : "f"(f1), "f"(f0));
    float r0 = f0 - __uint_as_float(h << 16);
    float r1 = f1 - __uint_as_float(h & 0xffff0000u);
    asm("cvt.rn.bf16x2.f32 %0, %1, %2;" : "=r"(l) : "f"(r1), "f"(r0));
}

__device__ __forceinline__ void mma_bf16(float* c, const uint32_t* a, const uint32_t* b) {
    asm volatile(
        "mma.sync.aligned.m16n8k16.row.col.f32.bf16.bf16.f32 "
        "{%0,%1,%2,%3}, {%4,%5,%6,%7}, {%8,%9}, {%0,%1,%2,%3};"
        : "+f"(c[0]), "+f"(c[1]), "+f"(c[2]), "+f"(c[3])
        : "r"(a[0]), "r"(a[1]), "r"(a[2]), "r"(a[3]), "r"(b[0]), "r"(b[1]));
}

// word-permute within each 8-word (k16) group so that the two MMA k-words a
// thread needs become adjacent (LDS.64), plus XOR swizzle by row group.
__device__ __forceinline__ int perm16(int w) {
    return (w & 8) | ((w & 3) << 1) | ((w >> 2) & 1);
}

// ---------------- edge dtype detection ----------------
__global__ void k_detect(const int* __restrict__ ei32) {
    __shared__ int any_nonzero;
    if (threadIdx.x == 0) any_nonzero = 0;
    __syncthreads();
    for (int i = threadIdx.x * 2 + 1; i < 8192; i += blockDim.x * 2) {
        if (ei32[i] != 0) any_nonzero = 1;
    }
    __syncthreads();
    if (threadIdx.x == 0) g_is64 = any_nonzero ? 0 : 1;
}

__device__ __forceinline__ void load_edge(const void* ei, int e, int& s, int& d) {
    if (g_is64) {
        const long long* p = (const long long*)ei;
        s = (int)p[e];
        d = (int)p[N_EDGES + e];
    } else {
        const int* p = (const int*)ei;
        s = p[e];
        d = p[N_EDGES + e];
    }
}

// ---------------- preprocessing ----------------
__global__ void k_zero() {
    int i = blockIdx.x * blockDim.x + threadIdx.x;
    if (i < N_GENES) g_row_deg[i] = 0;
    if (i < N_DRUGS) { g_col_deg[i] = 0; g_cursor[i] = 0; }
    if (i == 0) g_nactive = 0;
}

__global__ void k_degree(const void* __restrict__ ei) {
    int e = blockIdx.x * blockDim.x + threadIdx.x;
    if (e >= N_EDGES) return;
    int s, d;
    load_edge(ei, e, s, d);
    if (s >= 0 && s < N_GENES) atomicAdd(&g_row_deg[s], 1);
    if (d >= 0 && d < N_DRUGS) atomicAdd(&g_col_deg[d], 1);
}

__global__ void k_compact() {
    int g = blockIdx.x * blockDim.x + threadIdx.x;
    if (g >= N_GENES) return;
    int deg = g_row_deg[g];
    if (deg > 0) {
        int idx = atomicAdd(&g_nactive, 1);
        g_active[idx] = g;
        g_rowmap[g] = idx;
        g_rowscale[idx] = rsqrtf((float)deg);
    }
}

__global__ void k_scan() {
    __shared__ int sh[1024];
    int t = threadIdx.x;
    int base = t * 4;
    int v[4];
    int sum = 0;
#pragma unroll
    for (int i = 0; i < 4; i++) {
        v[i] = (base + i < N_DRUGS) ? g_col_deg[base + i] : 0;
        sum += v[i];
    }
    sh[t] = sum;
    __syncthreads();
    for (int d = 1; d < 1024; d <<= 1) {
        int x = (t >= d) ? sh[t - d] : 0;
        __syncthreads();
        sh[t] += x;
        __syncthreads();
    }
    int excl = (t > 0) ? sh[t - 1] : 0;
    int run = excl;
#pragma unroll
    for (int i = 0; i < 4; i++) {
        if (base + i < N_DRUGS) {
            g_offs[base + i] = run;
            run += v[i];
        }
    }
}

// place each edge's compact src index into the dst-sorted array
__global__ void k_place(const void* __restrict__ ei) {
    int e = blockIdx.x * blockDim.x + threadIdx.x;
    if (e >= N_EDGES) return;
    int s, d;
    load_edge(ei, e, s, d);
    if (s < 0 || s >= N_GENES || d < 0 || d >= N_DRUGS) return;
    int p = g_offs[d] + atomicAdd(&g_cursor[d], 1);
    g_sidx[p] = g_rowmap[s];
}

// ---------------- bf16x3 tensor-core GEMM ----------------
// g_xw[m, :] = rowscale[m] * (X[g_active[m], :] @ W), hi/lo bf16 split, 3 products.
// CTA 128x128, BK=32 (2 k16 steps), 8 warps each 64x32.
#define GM 128
#define GN 128
#define KT 32
#define NKT (IN_C / KT)   // 32

#define ROW_W   24                // words per row (16 used + pad)
#define PLANE_W (128 * ROW_W)     // 3072 words
#define AHI 0
#define ALO PLANE_W
#define BHI (2 * PLANE_W)
#define BLO (3 * PLANE_W)
#define BUF_W (4 * PLANE_W)       // 12288 words = 48KB
#define GEMM_SMEM (2 * BUF_W * 4) // 98304 B

__global__ __launch_bounds__(256) void k_gemm_bf16(const float* __restrict__ X,
                                                   const float* __restrict__ Wt) {
    const int nact = g_nactive;
    const int m0 = blockIdx.y * GM;
    if (m0 >= nact) return;
    const int n0 = blockIdx.x * GN;

    extern __shared__ __align__(16) uint32_t smem[];

    const int tid = threadIdx.x;
    const int wid = tid >> 5;
    const int lane = tid & 31;
    const int g = lane >> 2;
    const int tig = lane & 3;
    const int mwarp = (wid & 1) * 64;
    const int nwarp = (wid >> 1) * 32;

    // ---- A staging assignment: idx -> (m, float4-in-row) ----
    const float* aptr[4];
    int a_m[4], a_kq[4];
    bool a_ok[4];
#pragma unroll
    for (int p = 0; p < 4; p++) {
        int idx = p * 256 + tid;
        a_m[p] = idx >> 3;
        a_kq[p] = idx & 7;
        a_ok[p] = (m0 + a_m[p]) < nact;
        aptr[p] = a_ok[p] ? (X + (size_t)g_active[m0 + a_m[p]] * IN_C + a_kq[p] * 4) : X;
    }
    // ---- B staging assignment: t -> (n, 8 k-words) ----
    const int b_n = tid & 127;
    const int b_half = tid >> 7;              // which k16 step this thread fills
    const float* bptr = Wt + (size_t)(b_half * 16) * OUT_C + n0 + b_n;

    float acc[4][4][4];
#pragma unroll
    for (int i = 0; i < 4; i++)
#pragma unroll
        for (int j = 0; j < 4; j++)
#pragma unroll
            for (int r = 0; r < 4; r++) acc[i][j][r] = 0.f;

    float4 apre[4];
    float bpre[16];

    // prefetch k-tile 0
#pragma unroll
    for (int p = 0; p < 4; p++)
        apre[p] = a_ok[p] ? *(const float4*)(aptr[p]) : make_float4(0.f, 0.f, 0.f, 0.f);
#pragma unroll
    for (int j = 0; j < 16; j++) bpre[j] = bptr[(size_t)j * OUT_C];

    // store tile 0
    {
        uint32_t* buf = smem;
#pragma unroll
        for (int p = 0; p < 4; p++) {
            int m = a_m[p];
            int Xr = ((m >> 3) & 3) << 2;
            int w0 = a_kq[p] * 2;
            uint32_t h0, l0, h1, l1;
            split2_bf16(apre[p].x, apre[p].y, h0, l0);
            split2_bf16(apre[p].z, apre[p].w, h1, l1);
            int o0 = m * ROW_W + (perm16(w0) ^ Xr);
            int o1 = m * ROW_W + (perm16(w0 + 1) ^ Xr);
            buf[AHI + o0] = h0; buf[AHI + o1] = h1;
            buf[ALO + o0] = l0; buf[ALO + o1] = l1;
        }
        int Xn = ((b_n >> 3) & 3) << 2;
#pragma unroll
        for (int j = 0; j < 8; j++) {
            uint32_t h, l;
            split2_bf16(bpre[2 * j], bpre[2 * j + 1], h, l);
            int o = b_n * ROW_W + (perm16(b_half * 8 + j) ^ Xn);
            buf[BHI + o] = h;
            buf[BLO + o] = l;
        }
    }
    __syncthreads();

#pragma unroll 1
    for (int kt = 0; kt < NKT; kt++) {
        // prefetch next
        if (kt + 1 < NKT) {
#pragma unroll
            for (int p = 0; p < 4; p++)
                apre[p] = a_ok[p] ? *(const float4*)(aptr[p] + (kt + 1) * KT)
                                  : make_float4(0.f, 0.f, 0.f, 0.f);
#pragma unroll
            for (int j = 0; j < 16; j++)
                bpre[j] = bptr[(size_t)((kt + 1) * KT + j) * OUT_C];
        }

        // compute on current buffer
        const uint32_t* buf = smem + (kt & 1) * BUF_W;
#pragma unroll
        for (int ks = 0; ks < 2; ks++) {
            const int kb = ks * 8;
            const int wpos = kb + 2 * tig;   // even

            uint32_t ah[4][4], al[4][4], bh[4][2], bl[4][2];
#pragma unroll
            for (int mf = 0; mf < 4; mf++) {
                int r0 = mwarp + mf * 16 + g;
                int r1 = r0 + 8;
                int X0 = ((r0 >> 3) & 3) << 2;
                int X1 = ((r1 >> 3) & 3) << 2;
                uint2 h0 = *(const uint2*)&buf[AHI + r0 * ROW_W + (wpos ^ X0)];
                uint2 h1 = *(const uint2*)&buf[AHI + r1 * ROW_W + (wpos ^ X1)];
                uint2 l0 = *(const uint2*)&buf[ALO + r0 * ROW_W + (wpos ^ X0)];
                uint2 l1 = *(const uint2*)&buf[ALO + r1 * ROW_W + (wpos ^ X1)];
                ah[mf][0] = h0.x; ah[mf][1] = h1.x; ah[mf][2] = h0.y; ah[mf][3] = h1.y;
                al[mf][0] = l0.x; al[mf][1] = l1.x; al[mf][2] = l0.y; al[mf][3] = l1.y;
            }
#pragma unroll
            for (int nf = 0; nf < 4; nf++) {
                int n = nwarp + nf * 8 + g;
                int Xb = ((n >> 3) & 3) << 2;
                uint2 h = *(const uint2*)&buf[BHI + n * ROW_W + (wpos ^ Xb)];
                uint2 l = *(const uint2*)&buf[BLO + n * ROW_W + (wpos ^ Xb)];
                bh[nf][0] = h.x; bh[nf][1] = h.y;
                bl[nf][0] = l.x; bl[nf][1] = l.y;
            }
#pragma unroll
            for (int mf = 0; mf < 4; mf++) {
#pragma unroll
                for (int nf = 0; nf < 4; nf++) {
                    mma_bf16(acc[mf][nf], ah[mf], bh[nf]);
                    mma_bf16(acc[mf][nf], ah[mf], bl[nf]);
                    mma_bf16(acc[mf][nf], al[mf], bh[nf]);
                }
            }
        }

        // store next buffer
        if (kt + 1 < NKT) {
            uint32_t* nbuf = smem + ((kt + 1) & 1) * BUF_W;
#pragma unroll
            for (int p = 0; p < 4; p++) {
                int m = a_m[p];
                int Xr = ((m >> 3) & 3) << 2;
                int w0 = a_kq[p] * 2;
                uint32_t h0, l0, h1, l1;
                split2_bf16(apre[p].x, apre[p].y, h0, l0);
                split2_bf16(apre[p].z, apre[p].w, h1, l1);
                int o0 = m * ROW_W + (perm16(w0) ^ Xr);
                int o1 = m * ROW_W + (perm16(w0 + 1) ^ Xr);
                nbuf[AHI + o0] = h0; nbuf[AHI + o1] = h1;
                nbuf[ALO + o0] = l0; nbuf[ALO + o1] = l1;
            }
            int Xn = ((b_n >> 3) & 3) << 2;
#pragma unroll
            for (int j = 0; j < 8; j++) {
                uint32_t h, l;
                split2_bf16(bpre[2 * j], bpre[2 * j + 1], h, l);
                int o = b_n * ROW_W + (perm16(b_half * 8 + j) ^ Xn);
                nbuf[BHI + o] = h;
                nbuf[BLO + o] = l;
            }
        }
        __syncthreads();
    }

    // ---- epilogue: apply row scale, store float2 ----
#pragma unroll
    for (int mf = 0; mf < 4; mf++) {
        int r0 = m0 + mwarp + mf * 16 + g;
        int r1 = r0 + 8;
        float s0 = (r0 < nact) ? g_rowscale[r0] : 0.f;
        float s1 = (r1 < nact) ? g_rowscale[r1] : 0.f;
#pragma unroll
        for (int nf = 0; nf < 4; nf++) {
            int col = n0 + nwarp + nf * 8 + tig * 2;
            if (r0 < nact)
                *(float2*)(g_xw + (size_t)r0 * OUT_C + col) =
                    make_float2(acc[mf][nf][0] * s0, acc[mf][nf][1] * s0);
            if (r1 < nact)
                *(float2*)(g_xw + (size_t)r1 * OUT_C + col) =
                    make_float2(acc[mf][nf][2] * s1, acc[mf][nf][3] * s1);
        }
    }
}

// ---------------- aggregation: pure sum, dst scale at the end ----------------
__global__ __launch_bounds__(128) void k_aggregate(const float* __restrict__ bias,
                                                   float* __restrict__ out) {
    int d = blockIdx.x;
    int t = threadIdx.x;
    int beg = g_offs[d];
    int n = g_col_deg[d];
    int end = beg + n;
    const float4* xw4 = (const float4*)g_xw;

    float4 a0 = make_float4(0.f, 0.f, 0.f, 0.f);
    float4 a1 = a0, a2 = a0, a3 = a0;
    int i = beg;
    for (; i + 3 < end; i += 4) {
        int s0 = g_sidx[i], s1 = g_sidx[i + 1], s2 = g_sidx[i + 2], s3 = g_sidx[i + 3];
        float4 v0 = xw4[(size_t)s0 * (OUT_C / 4) + t];
        float4 v1 = xw4[(size_t)s1 * (OUT_C / 4) + t];
        float4 v2 = xw4[(size_t)s2 * (OUT_C / 4) + t];
        float4 v3 = xw4[(size_t)s3 * (OUT_C / 4) + t];
        a0.x += v0.x; a0.y += v0.y; a0.z += v0.z; a0.w += v0.w;
        a1.x += v1.x; a1.y += v1.y; a1.z += v1.z; a1.w += v1.w;
        a2.x += v2.x; a2.y += v2.y; a2.z += v2.z; a2.w += v2.w;
        a3.x += v3.x; a3.y += v3.y; a3.z += v3.z; a3.w += v3.w;
    }
    for (; i < end; i++) {
        int s0 = g_sidx[i];
        float4 v0 = xw4[(size_t)s0 * (OUT_C / 4) + t];
        a0.x += v0.x; a0.y += v0.y; a0.z += v0.z; a0.w += v0.w;
    }
    float cs = (n > 0) ? rsqrtf((float)n) : 0.f;
    float4 b = ((const float4*)bias)[t];
    float4 o = make_float4((a0.x + a1.x + a2.x + a3.x) * cs + b.x,
                           (a0.y + a1.y + a2.y + a3.y) * cs + b.y,
                           (a0.z + a1.z + a2.z + a3.z) * cs + b.z,
                           (a0.w + a1.w + a2.w + a3.w) * cs + b.w);
    ((float4*)out)[(size_t)d * (OUT_C / 4) + t] = o;
}

// ---------------- launch ----------------
extern "C" void kernel_launch(void* const* d_in, const int* in_sizes, int n_in,
                              void* d_out, int out_size) {
    const float* x = (const float*)d_in[0];
    const float* w = (const float*)d_in[1];
    const float* bias = (const float*)d_in[2];
    const void* ei = d_in[3];
    float* out = (float*)d_out;

    static bool attr_set = false;
    if (!attr_set) {
        cudaFuncSetAttribute(k_gemm_bf16, cudaFuncAttributeMaxDynamicSharedMemorySize,
                             GEMM_SMEM);
        attr_set = true;
    }

    k_detect<<<1, 256>>>((const int*)ei);
    k_zero<<<(N_GENES + 255) / 256, 256>>>();
    k_degree<<<(N_EDGES + 255) / 256, 256>>>(ei);
    k_compact<<<(N_GENES + 255) / 256, 256>>>();
    k_scan<<<1, 1024>>>();
    k_place<<<(N_EDGES + 255) / 256, 256>>>(ei);

    dim3 gemm_grid(OUT_C / GN, (N_GENES + GM - 1) / GM);
    k_gemm_bf16<<<gemm_grid, 256, GEMM_SMEM>>>(x, w);

    k_aggregate<<<N_DRUGS, 128>>>(bias, out);
}